// round 10
// baseline (speedup 1.0000x reference)
#include <cuda_runtime.h>

// Problem constants
#define BN    4096
#define NFEAT 1024
#define RR    64
#define KK    32
#define DD    16
#define NRD   (RR * DD)        // 1024 (r,d) pairs

#define LOG_2PI_F 1.8378770664093453f

// Main-kernel tiling
#define BT      8              // b rows per warp-tile
#define NTILES  (BN / BT)      // 512
#define MGX     6              // main grid.x -> (6,64)=384 blocks <= 444 cap
#define WSTRIDE (MGX * 8)      // 48 warp slots per region

// Gather-kernel tiling
#define GB      64             // b rows per gather block
#define GC      128            // columns per gather block
#define NBIN    (NFEAT / GC)   // 8 column bins

typedef unsigned long long u64;

// Packed fp32x2 helpers (sm_103a FFMA2 — only reachable via PTX)
__device__ __forceinline__ u64 ffma2(u64 a, u64 b, u64 c) {
    u64 d;
    asm("fma.rn.f32x2 %0, %1, %2, %3;" : "=l"(d) : "l"(a), "l"(b), "l"(c));
    return d;
}
__device__ __forceinline__ u64 bcast2(float v) {
    u64 d;
    unsigned int r = __float_as_uint(v);
    asm("mov.b64 %0, {%1, %1};" : "=l"(d) : "r"(r));
    return d;
}
__device__ __forceinline__ void unpack2(u64 v, float& lo, float& hi) {
    unsigned int a, b;
    asm("mov.b64 {%0, %1}, %2;" : "=r"(a), "=r"(b) : "l"(v));
    lo = __uint_as_float(a);
    hi = __uint_as_float(b);
}

// Device globals (no runtime allocation allowed)
__device__ int   g_srt_rd [NRD];          // entries sorted by column bin
__device__ int   g_srt_col[NRD];
__device__ int   g_bin_start[NBIN + 1];
__device__ float g_xg[(size_t)NRD * BN];  // [rd][b] pre-gathered x (16.8 MB)

// ---------------------------------------------------------------------------
// Index kernel: ONE block x 512 threads. Extracts region indices
// (int64/int32 auto-detect) and counting-sorts (rd, col) by column bin.
// ---------------------------------------------------------------------------
__global__ void idx_kernel(const void* __restrict__ regions_raw) {
    __shared__ int s_or;
    __shared__ int s_cnt[NBIN];
    __shared__ int s_pos[NBIN];

    const int t = threadIdx.x;       // 0..511

    if (t == 0) s_or = 0;
    if (t < NBIN) s_cnt[t] = 0;
    __syncthreads();

    // int64 detection: values < 1024, so if int64 every odd word is 0.
    const int* w = (const int*)regions_raw;
    int v = w[2 * t + 1];
#pragma unroll
    for (int o = 16; o >= 1; o >>= 1)
        v |= __shfl_xor_sync(0xffffffffu, v, o);
    if ((t & 31) == 0) atomicOr(&s_or, v);
    __syncthreads();

    const int is64 = (s_or == 0);
    const int c0 = is64 ? w[4 * t]     : w[2 * t];
    const int c1 = is64 ? w[4 * t + 2] : w[2 * t + 1];

    atomicAdd(&s_cnt[c0 >> 7], 1);
    atomicAdd(&s_cnt[c1 >> 7], 1);
    __syncthreads();
    if (t == 0) {
        int acc = 0;
        for (int bb = 0; bb < NBIN; bb++) {
            g_bin_start[bb] = acc;
            s_pos[bb] = acc;
            acc += s_cnt[bb];
        }
        g_bin_start[NBIN] = acc;     // == 1024
    }
    __syncthreads();
    int p0 = atomicAdd(&s_pos[c0 >> 7], 1);
    g_srt_rd[p0] = 2 * t;      g_srt_col[p0] = c0;
    int p1 = atomicAdd(&s_pos[c1 >> 7], 1);
    g_srt_rd[p1] = 2 * t + 1;  g_srt_col[p1] = c1;
}

// ---------------------------------------------------------------------------
// Gather: build g_xg[rd][b]. Grid (BN/GB=64, NBIN=8), 256 threads.
// Load x[b0:b0+64][c0:c0+128] into an XOR-swizzled smem tile (conflict-free
// column reads), then for each sorted entry in this bin write 64 consecutive
// b's (256B coalesced) to g_xg.
// ---------------------------------------------------------------------------
__global__ __launch_bounds__(256)
void gather_kernel(const float* __restrict__ x) {
    __shared__ float sx[GB * GC];    // 32 KB, float-XOR swizzled

    const int t  = threadIdx.x;
    const int b0 = blockIdx.x * GB;
    const int cc = blockIdx.y;
    const int c0 = cc * GC;

    // sx[row*GC + (c ^ (row & 31))] = x[b0+row][c0+c]
#pragma unroll
    for (int i = 0; i < GB * GC / 256; i++) {   // 32 iters
        const int g   = i * 256 + t;
        const int row = g >> 7;                 // / GC
        const int c   = g & (GC - 1);
        sx[row * GC + (c ^ (row & 31))] =
            x[(size_t)(b0 + row) * NFEAT + c0 + c];
    }
    __syncthreads();

    // Entries for this column bin: 4 entries x 64 b's per iteration
    const int e0  = g_bin_start[cc];
    const int e1  = g_bin_start[cc + 1];
    const int sub = t >> 6;       // 0..3
    const int b   = t & 63;
    for (int e = e0 + sub; e < e1; e += 4) {
        const int rd  = g_srt_rd[e];
        const int col = g_srt_col[e] - c0;
        g_xg[(size_t)rd * BN + b0 + b] = sx[b * GC + (col ^ (b & 31))];
    }
}

// ---------------------------------------------------------------------------
// Main: grid (6, 64), 256 threads = 8 independent warps, NO barriers, NO smem.
// Warp = region blockIdx.y; warp slot wg = blockIdx.x*8 + w; tiles
// t = wg + j*48. Lane k computes 8b x 1k.
//  - weights computed IN-KERNEL once per block (16 div + 16 logf per lane)
//  - x read via warp-uniform LDG.128 from L2-resident g_xg (1 sector/request)
//  - pure FFMA2 inner loop
// ---------------------------------------------------------------------------
__global__ __launch_bounds__(256, 3)
void main_kernel(const float* __restrict__ means,
                 const float* __restrict__ scales,
                 float* __restrict__ out) {
    const int tid  = threadIdx.x;
    const int w    = tid >> 5;
    const int lane = tid & 31;
    const int r    = blockIdx.y;
    const int k    = lane;

    // ---- In-kernel weight computation (once per block, per lane) ----
    float wa[DD], wb[DD];
    float lsum = 0.0f;
    {
        const float* sp = scales + ((size_t)r * KK + k) * DD;
        const float* mp = means  + ((size_t)r * KK + k) * DD;
#pragma unroll
        for (int d = 0; d < DD; d++) {
            const float s   = sp[d];
            const float inv = 1.0f / s;
            wa[d] = inv;
            wb[d] = -mp[d] * inv;
            lsum += logf(s);
        }
    }
    const u64 cc = bcast2(-lsum - 0.5f * (float)DD * LOG_2PI_F);
    const u64 nh = bcast2(-0.5f);

    const float* xgr = g_xg + (size_t)r * DD * BN;
    const int wg = blockIdx.x * 8 + w;            // 0..47

    // ---- Per-warp tile loop: zero barriers, warp-uniform LDG ----
    for (int t = wg; t < NTILES; t += WSTRIDE) {
        const float* xb = xgr + (size_t)t * BT;

        u64 acc[4];
#pragma unroll
        for (int p = 0; p < 4; p++) acc[p] = 0ull;

#pragma unroll
        for (int d = 0; d < DD; d++) {
            // 8 b's for this (r,d): two uniform LDG.128 (broadcast)
            const ulonglong2 xA = __ldg((const ulonglong2*)(xb + (size_t)d * BN));
            const ulonglong2 xB = __ldg((const ulonglong2*)(xb + (size_t)d * BN + 4));
            const u64 aa = bcast2(wa[d]);
            const u64 bb = bcast2(wb[d]);
            u64 z;
            z = ffma2(xA.x, aa, bb); acc[0] = ffma2(z, z, acc[0]);
            z = ffma2(xA.y, aa, bb); acc[1] = ffma2(z, z, acc[1]);
            z = ffma2(xB.x, aa, bb); acc[2] = ffma2(z, z, acc[2]);
            z = ffma2(xB.y, aa, bb); acc[3] = ffma2(z, z, acc[3]);
        }

        // ---- Epilogue: out[b][r][k], lanes coalesce over k ----
        float* op = out + (size_t)t * BT * (RR * KK) + r * KK + k;
#pragma unroll
        for (int p = 0; p < 4; p++) {
            const u64 o = ffma2(acc[p], nh, cc);
            float lo, hi;
            unpack2(o, lo, hi);
            op[(size_t)(2 * p)     * (RR * KK)] = lo;
            op[(size_t)(2 * p + 1) * (RR * KK)] = hi;
        }
    }
}

// ---------------------------------------------------------------------------
extern "C" void kernel_launch(void* const* d_in, const int* in_sizes, int n_in,
                              void* d_out, int out_size) {
    const float* x       = (const float*)d_in[0];
    const void*  regions = d_in[1];                // int64 or int32, detected
    const float* means   = (const float*)d_in[2];
    const float* scales  = (const float*)d_in[3];
    float*       out     = (float*)d_out;

    idx_kernel<<<1, 512>>>(regions);
    gather_kernel<<<dim3(BN / GB, NBIN), 256>>>(x);
    main_kernel<<<dim3(MGX, RR), 256>>>(means, scales, out);
}

// round 11
// speedup vs baseline: 1.6026x; 1.6026x over previous
#include <cuda_runtime.h>

// Problem constants
#define BN    4096
#define NFEAT 1024
#define RR    64
#define KK    32
#define DD    16

// Tiling
#define BT      8       // b rows per tile
#define RG      16      // regions per block
#define THREADS 256
#define GRIDX   74      // 74 x 4 groups = 296 blocks = 2 per SM
#define NTILES  (BN / BT)   // 512 b-tiles
#define DEPTH   3       // cp.async ring depth

#define XPITCH 1028     // smem pitch for raw x rows (bank-decorrelated gather)
#define GPITCH 132      // smem pitch per region for gathered tile [d][b]

#define LOG_2PI_F 1.8378770664093453f

typedef unsigned long long u64;

// Packed fp32x2 helpers (sm_103a FFMA2 — only reachable via PTX)
__device__ __forceinline__ u64 ffma2(u64 a, u64 b, u64 c) {
    u64 d;
    asm("fma.rn.f32x2 %0, %1, %2, %3;" : "=l"(d) : "l"(a), "l"(b), "l"(c));
    return d;
}
__device__ __forceinline__ u64 bcast2(float v) {
    u64 d;
    unsigned int r = __float_as_uint(v);
    asm("mov.b64 %0, {%1, %1};" : "=l"(d) : "r"(r));
    return d;
}
__device__ __forceinline__ void unpack2(u64 v, float& lo, float& hi) {
    unsigned int a, b;
    asm("mov.b64 {%0, %1}, %2;" : "=r"(a), "=r"(b) : "l"(v));
    lo = __uint_as_float(a);
    hi = __uint_as_float(b);
}
__device__ __forceinline__ unsigned int smem_u32(const void* p) {
    unsigned int a;
    asm("{ .reg .u64 t; cvta.to.shared.u64 t, %1; cvt.u32.u64 %0, t; }"
        : "=r"(a) : "l"(p));
    return a;
}

// Precomputed parameters (device globals: no allocation allowed)
__device__ float g_wa[RR * DD * KK];   // [r][d][k] = 1/scale
__device__ float g_wb[RR * DD * KK];   // [r][d][k] = -mean/scale
__device__ float g_c [RR * KK];        // [r][k]
__device__ int   g_idx[RR * DD];       // region indices as int32

// ---------------------------------------------------------------------------
// Prep kernel: 64 blocks (one per region) x 512 threads.
// ---------------------------------------------------------------------------
__global__ void prep_kernel(const float* __restrict__ means,
                            const float* __restrict__ scales,
                            const void*  __restrict__ regions_raw) {
    const int r = blockIdx.x;
    const int t = threadIdx.x;       // 0..511
    const int k = t >> 4;
    const int d = t & 15;

    const float s   = scales[((size_t)r * KK + k) * DD + d];
    const float m   = means [((size_t)r * KK + k) * DD + d];
    const float inv = 1.0f / s;
    g_wa[(r * DD + d) * KK + k] = inv;
    g_wb[(r * DD + d) * KK + k] = -m * inv;

    float lg = logf(s);
#pragma unroll
    for (int o = 8; o >= 1; o >>= 1)
        lg += __shfl_xor_sync(0xffffffffu, lg, o);
    if (d == 0)
        g_c[r * KK + k] = -lg - 0.5f * (float)DD * LOG_2PI_F;

    if (r == 0) {
        // int64 detection: if regions is int64 (values < 1024), every odd
        // 32-bit word is zero.
        __shared__ int s_or;
        if (t == 0) s_or = 0;
        __syncthreads();
        const int* w = (const int*)regions_raw;
        int v = w[2 * t + 1];
#pragma unroll
        for (int o = 16; o >= 1; o >>= 1)
            v |= __shfl_xor_sync(0xffffffffu, v, o);
        if ((t & 31) == 0) atomicOr(&s_or, v);
        __syncthreads();
        const int is64 = (s_or == 0);
        g_idx[2 * t]     = is64 ? w[4 * t]     : w[2 * t];
        g_idx[2 * t + 1] = is64 ? w[4 * t + 2] : w[2 * t + 1];
    }
}

// ---------------------------------------------------------------------------
// Main kernel: persistent blocks, grid = (74, 4) = 296 = 2 blocks/SM.
// Block (bx, g): r-group g (16 regions), b-tiles t = bx + j*74.
//  - weights (all 16 d) + gather indices loaded ONCE per block
//  - THREE-deep cp.async ring over b-tiles: the load completed by
//    wait_group 2 was issued two tile-times earlier -> latency fully hidden
//  - thread (rl = tid>>4, kp = tid&15): 8b x 2k tile, packed FFMA2
// ---------------------------------------------------------------------------
__global__ __launch_bounds__(THREADS, 2)
void main_kernel(const float* __restrict__ x, float* __restrict__ out) {
    extern __shared__ float smem[];
    float* sm_xb[DEPTH];
    sm_xb[0] = smem;
    sm_xb[1] = smem + BT * XPITCH;
    sm_xb[2] = smem + 2 * BT * XPITCH;
    float* sm_xg  = smem + DEPTH * BT * XPITCH;   // RG*GPITCH
    int*   sm_idx = (int*)(sm_xg + RG * GPITCH);  // RG*DD = 256

    const int tid = threadIdx.x;
    const int r0  = blockIdx.y * RG;

    const int rl = tid >> 4;         // region within block: 0..15
    const int kp = tid & 15;         // k-pair index: k0 = kp*2
    const int r  = r0 + rl;
    const int k0 = kp * 2;

    // ---- One-time: gather indices to smem; weights to registers ----
    sm_idx[tid] = g_idx[r0 * DD + tid];          // 256 == RG*DD

    float2 wa2[DD], wb2[DD];
    {
        const float* wap = g_wa + r * DD * KK + k0;
        const float* wbp = g_wb + r * DD * KK + k0;
#pragma unroll
        for (int d = 0; d < DD; d++) {
            wa2[d] = *(const float2*)(wap + d * KK);
            wb2[d] = *(const float2*)(wbp + d * KK);
        }
    }
    const float2 c2 = *(const float2*)&g_c[r * KK + k0];

    unsigned int s_xb[DEPTH];
#pragma unroll
    for (int p = 0; p < DEPTH; p++) s_xb[p] = smem_u32(sm_xb[p]);

    // ---- Prologue: issue loads for tiles t0, t0+G into bufs 0, 1 ----
    const int t0 = blockIdx.x;
#pragma unroll
    for (int p = 0; p < DEPTH - 1; p++) {
        const int tp = t0 + p * GRIDX;
        if (tp < NTILES) {
            const float* xrow = x + (size_t)tp * BT * NFEAT;
#pragma unroll
            for (int i = tid; i < BT * (NFEAT / 4); i += THREADS) {
                const int row = i >> 8;
                const int c   = i & 255;
                const unsigned int dst =
                    s_xb[p] + (unsigned)(row * XPITCH + c * 4) * 4u;
                asm volatile("cp.async.cg.shared.global [%0], [%1], 16;"
                             :: "r"(dst), "l"(xrow + (size_t)row * NFEAT + c * 4));
            }
        }
        asm volatile("cp.async.commit_group;" ::: "memory");
    }

    // ---- Pipelined tile loop ----
    int bufj = 0;                                  // j % 3
    for (int j = 0, t = t0; t < NTILES; j++, t += GRIDX) {
        // Issue load for tile t+2G into buf (j+2)%3 (the buffer whose last
        // reader was gather(j-1), already fenced by its closing barrier).
        const int tf = t + (DEPTH - 1) * GRIDX;
        int buff = bufj + 2; if (buff >= DEPTH) buff -= DEPTH;
        if (tf < NTILES) {
            const float* xrow = x + (size_t)tf * BT * NFEAT;
#pragma unroll
            for (int i = tid; i < BT * (NFEAT / 4); i += THREADS) {
                const int row = i >> 8;
                const int c   = i & 255;
                const unsigned int dst =
                    s_xb[buff] + (unsigned)(row * XPITCH + c * 4) * 4u;
                asm volatile("cp.async.cg.shared.global [%0], [%1], 16;"
                             :: "r"(dst), "l"(xrow + (size_t)row * NFEAT + c * 4));
            }
        }
        asm volatile("cp.async.commit_group;" ::: "memory");
        // Oldest group (tile t, issued 2 iterations ago) must be complete.
        asm volatile("cp.async.wait_group 2;" ::: "memory");
        __syncthreads();

        // ---- Gather tile t into sm_xg[rg][d*BT + b] ----
        const float* sm_cur = sm_xb[bufj];
#pragma unroll
        for (int jj = 0; jj < 8; jj++) {
            const int e  = tid + jj * THREADS;
            const int b  = e & (BT - 1);
            const int d  = (e >> 3) & (DD - 1);
            const int rg = e >> 7;
            const int col = sm_idx[rg * DD + d];
            sm_xg[rg * GPITCH + d * BT + b] = sm_cur[b * XPITCH + col];
        }
        __syncthreads();

        // ---- Compute: per d, 2 LDS.128 (broadcast) + 4 mov + 16 FFMA2 ----
        const float* xp = sm_xg + rl * GPITCH;

        u64 acc0[4], acc1[4];
#pragma unroll
        for (int p = 0; p < 4; p++) { acc0[p] = 0ull; acc1[p] = 0ull; }

#pragma unroll
        for (int d = 0; d < DD; d++) {
            const ulonglong2 xA = *(const ulonglong2*)(xp + d * BT);
            const ulonglong2 xB = *(const ulonglong2*)(xp + d * BT + 4);
            const u64 xv[4] = {xA.x, xA.y, xB.x, xB.y};

            const u64 aa0 = bcast2(wa2[d].x);
            const u64 aa1 = bcast2(wa2[d].y);
            const u64 bb0 = bcast2(wb2[d].x);
            const u64 bb1 = bcast2(wb2[d].y);
#pragma unroll
            for (int p = 0; p < 4; p++) {
                const u64 z0 = ffma2(xv[p], aa0, bb0);
                acc0[p] = ffma2(z0, z0, acc0[p]);
                const u64 z1 = ffma2(xv[p], aa1, bb1);
                acc1[p] = ffma2(z1, z1, acc1[p]);
            }
        }

        // ---- Epilogue: out[b][r][k0..k0+1] = -0.5*acc + C ----
        const int b0 = t * BT;
        const u64 nh  = bcast2(-0.5f);
        const u64 cc0 = bcast2(c2.x);
        const u64 cc1 = bcast2(c2.y);
#pragma unroll
        for (int p = 0; p < 4; p++) {
            const u64 o0 = ffma2(acc0[p], nh, cc0);
            const u64 o1 = ffma2(acc1[p], nh, cc1);
            float o0lo, o0hi, o1lo, o1hi;
            unpack2(o0, o0lo, o0hi);
            unpack2(o1, o1lo, o1hi);
            *(float2*)&out[((size_t)(b0 + 2 * p)     * RR + r) * KK + k0] =
                make_float2(o0lo, o1lo);
            *(float2*)&out[((size_t)(b0 + 2 * p + 1) * RR + r) * KK + k0] =
                make_float2(o0hi, o1hi);
        }

        if (++bufj == DEPTH) bufj = 0;
    }
}

// ---------------------------------------------------------------------------
#define SMEM_BYTES ((DEPTH * BT * XPITCH + RG * GPITCH) * 4 + RG * DD * 4)

extern "C" void kernel_launch(void* const* d_in, const int* in_sizes, int n_in,
                              void* d_out, int out_size) {
    const float* x       = (const float*)d_in[0];
    const void*  regions = d_in[1];                // int64 or int32, detected
    const float* means   = (const float*)d_in[2];
    const float* scales  = (const float*)d_in[3];
    float*       out     = (float*)d_out;

    cudaFuncSetAttribute(main_kernel,
                         cudaFuncAttributeMaxDynamicSharedMemorySize,
                         SMEM_BYTES);

    prep_kernel<<<RR, 512>>>(means, scales, regions);

    dim3 grid(GRIDX, RR / RG);
    main_kernel<<<grid, THREADS, SMEM_BYTES>>>(x, out);
}